// round 2
// baseline (speedup 1.0000x reference)
#include <cuda_runtime.h>
#include <cuda_bf16.h>
#include <cstdint>

#define BB 2
#define LL 2048
#define TT 4096
#define DM 512
#define DIN 1024
#define NH 16
#define HD 64
#define DS 64
#define DCONV 1152
#define DPROJ 2192
#define EPSF 1e-5f
#define CH 16

// ---------------- scratch (static __device__ arrays; allocation-free) ----------------
__device__ float g_xn[TT * DM];
__device__ float g_zx0[TT * DPROJ];
__device__ float g_zx1[TT * DPROJ];
__device__ float g_xbc0[TT * DCONV];
__device__ float g_xbc1[TT * DCONV];
__device__ float g_dt[2 * BB * NH * LL];
__device__ float g_dA[2 * BB * NH * LL];
__device__ float g_ys0[TT * DIN];
__device__ float g_ys1[TT * DIN];
__device__ float g_yn0[TT * DIN];
__device__ float g_yn1[TT * DIN];
__device__ float g_od0[TT * DM];
__device__ float g_od1[TT * DM];

// ---------------- input rmsnorm: xn = rmsnorm(x) * norm_w ----------------
__global__ void rms_x_kernel(const float* __restrict__ x, const float* __restrict__ nw,
                             float* __restrict__ xn) {
    int t = blockIdx.x;
    int tid = threadIdx.x;
    float v[4];
    float ss = 0.f;
#pragma unroll
    for (int it = 0; it < 4; it++) {
        v[it] = x[(size_t)t * DM + tid + it * 128];
        ss += v[it] * v[it];
    }
#pragma unroll
    for (int o = 16; o > 0; o >>= 1) ss += __shfl_xor_sync(~0u, ss, o);
    __shared__ float ws[4];
    if ((tid & 31) == 0) ws[tid >> 5] = ss;
    __syncthreads();
    float tot = ws[0] + ws[1] + ws[2] + ws[3];
    float sc = rsqrtf(tot / (float)DM + EPSF);
#pragma unroll
    for (int it = 0; it < 4; it++) {
        int j = tid + it * 128;
        xn[(size_t)t * DM + j] = v[it] * sc * nw[j];
    }
}

// ---------------- generic NT GEMM: C[m,n] = sum_k A[m,k] * W[n,k] ----------------
// mode 0: A row = m
// mode 1: A row = flipped within batch (b, 2047-s)   (bwd in-proj)
// mode 2: concat final proj: k<512 from A (row m), k>=512 from A2 (row flipped), both stride 512
// N may not be a multiple of 64 (in-proj N=2192): W loads and C stores are guarded.
__global__ __launch_bounds__(256) void gemm_nt(
    const float* __restrict__ A, const float* __restrict__ A2,
    const float* __restrict__ W, float* __restrict__ C,
    int N, int K, int mode,
    const float* __restrict__ bias, const float* __restrict__ resid) {
    __shared__ float sA[16][64];
    __shared__ float sB[16][64];
    int tid = threadIdx.x;
    int m0 = blockIdx.y * 64, n0 = blockIdx.x * 64;
    int ty = tid >> 4, tx = tid & 15;
    int lrow = tid >> 2, lk = (tid & 3) * 4;
    float acc[4][4];
#pragma unroll
    for (int i = 0; i < 4; i++)
#pragma unroll
        for (int j = 0; j < 4; j++) acc[i][j] = 0.f;

    for (int k0 = 0; k0 < K; k0 += 16) {
        float4 av;
        int gr = m0 + lrow;
        if (mode == 2) {
            int bb = gr >> 11, s = gr & 2047;
            if (k0 < 512)
                av = *(const float4*)(A + (size_t)gr * 512 + k0 + lk);
            else
                av = *(const float4*)(A2 + (size_t)((bb << 11) + (2047 - s)) * 512 + (k0 - 512) + lk);
        } else {
            int row = gr;
            if (mode == 1) {
                int bb = gr >> 11, s = gr & 2047;
                row = (bb << 11) + (2047 - s);
            }
            av = *(const float4*)(A + (size_t)row * K + k0 + lk);
        }
        float4 wv = make_float4(0.f, 0.f, 0.f, 0.f);
        if (n0 + lrow < N)
            wv = *(const float4*)(W + (size_t)(n0 + lrow) * K + k0 + lk);
        sA[lk + 0][lrow] = av.x; sA[lk + 1][lrow] = av.y;
        sA[lk + 2][lrow] = av.z; sA[lk + 3][lrow] = av.w;
        sB[lk + 0][lrow] = wv.x; sB[lk + 1][lrow] = wv.y;
        sB[lk + 2][lrow] = wv.z; sB[lk + 3][lrow] = wv.w;
        __syncthreads();
#pragma unroll
        for (int kk = 0; kk < 16; kk++) {
            float a[4], b[4];
            *(float4*)a = *(const float4*)&sA[kk][ty * 4];
            *(float4*)b = *(const float4*)&sB[kk][tx * 4];
#pragma unroll
            for (int i = 0; i < 4; i++)
#pragma unroll
                for (int j = 0; j < 4; j++) acc[i][j] = fmaf(a[i], b[j], acc[i][j]);
        }
        __syncthreads();
    }
#pragma unroll
    for (int i = 0; i < 4; i++) {
        int m = m0 + ty * 4 + i;
#pragma unroll
        for (int j = 0; j < 4; j++) {
            int n = n0 + tx * 4 + j;
            if (n >= N) continue;
            float v = acc[i][j];
            if (bias) v += bias[n];
            if (resid) v += resid[(size_t)m * N + n];
            C[(size_t)m * N + n] = v;
        }
    }
}

// ---------------- causal depthwise conv (width 4) + bias + SiLU ----------------
__global__ void conv_silu_kernel(const float* __restrict__ zx0, const float* __restrict__ zx1,
                                 const float* __restrict__ cwf, const float* __restrict__ cbf,
                                 const float* __restrict__ cwb, const float* __restrict__ cbb,
                                 float* __restrict__ xbc0, float* __restrict__ xbc1) {
    int idx = blockIdx.x * blockDim.x + threadIdx.x;
    const int per = TT * DCONV;
    if (idx >= 2 * per) return;
    int d = idx / per;
    int r = idx - d * per;
    int t = r / DCONV;
    int c = r - t * DCONV;
    int b = t >> 11, s = t & 2047;
    const float* zx = d ? zx1 : zx0;
    const float* cw = d ? cwb : cwf;
    const float* cb = d ? cbb : cbf;
    float acc = cb[c];
#pragma unroll
    for (int i = 0; i < 4; i++) {
        int ss = s - 3 + i;
        if (ss >= 0)
            acc = fmaf(cw[c * 4 + i], zx[(size_t)((b << 11) + ss) * DPROJ + DIN + c], acc);
    }
    float v = acc / (1.f + expf(-acc));
    (d ? xbc1 : xbc0)[(size_t)t * DCONV + c] = v;
}

// ---------------- dt/dA precompute ----------------
__global__ void dt_kernel(const float* __restrict__ zx0, const float* __restrict__ zx1,
                          const float* __restrict__ dtbf, const float* __restrict__ Alf,
                          const float* __restrict__ dtbb, const float* __restrict__ Alb,
                          float* __restrict__ dtg, float* __restrict__ dAg) {
    int idx = blockIdx.x * blockDim.x + threadIdx.x;
    if (idx >= 2 * TT * NH) return;
    int d = idx / (TT * NH);
    int r = idx - d * TT * NH;
    int t = r / NH;
    int h = r - t * NH;
    int b = t >> 11, s = t & 2047;
    const float* zx = d ? zx1 : zx0;
    float raw = zx[(size_t)t * DPROJ + (DPROJ - NH) + h] + (d ? dtbb : dtbf)[h];
    float dtv = (raw > 20.f) ? raw : log1pf(expf(raw));
    float dAv = expf(-expf((d ? Alb : Alf)[h]) * dtv);
    int row = ((d * BB + b) * NH + h);
    dtg[(size_t)row * LL + s] = dtv;
    dAg[(size_t)row * LL + s] = dAv;
}

// ---------------- sequential SSM scan, one CTA per (dir, b, head) ----------------
// 256 threads: thread owns p = tid>>2 (headdim row), q = tid&3 -> 16 states n in [q*16, q*16+16)
// cp.async double-buffered chunks of CH=16 timesteps.
__global__ __launch_bounds__(256) void scan_kernel(
    const float* __restrict__ xbc0, const float* __restrict__ xbc1,
    const float* __restrict__ dtg, const float* __restrict__ dAg,
    const float* __restrict__ Df, const float* __restrict__ Db,
    float* __restrict__ ys0, float* __restrict__ ys1) {
    int bid = blockIdx.x;
    int d = bid >> 5;
    int b = (bid >> 4) & 1;
    int hh = bid & 15;
    const float* xbc = d ? xbc1 : xbc0;
    float* ys = d ? ys1 : ys0;
    float Dh = (d ? Db : Df)[hh];
    int tid = threadIdx.x;
    int p = tid >> 2, q = tid & 3;
    int scrow = ((d * BB + b) * NH + hh) * LL;

    __shared__ float4 sxs[2][CH][16];   // xs: 64 floats/step
    __shared__ float4 sbc[2][CH][32];   // B (64) then C (64) per step
    __shared__ float4 sdA[2][4];
    __shared__ float4 sdt[2][4];

    auto issue_chunk = [&](int c, int buf) {
        int s0 = c * CH;
        for (int ii = tid; ii < 776; ii += 256) {
            const float* src;
            void* dst;
            if (ii < 768) {
                int j = ii / 48, w = ii - j * 48;
                size_t rowb = (size_t)((b << 11) + s0 + j) * DCONV;
                if (w < 16) { src = xbc + rowb + hh * 64 + w * 4; dst = &sxs[buf][j][w]; }
                else        { src = xbc + rowb + 1024 + (w - 16) * 4; dst = &sbc[buf][j][w - 16]; }
            } else {
                int k2 = ii - 768;
                if (k2 < 4) { src = dAg + (size_t)scrow + s0 + k2 * 4; dst = &sdA[buf][k2]; }
                else        { src = dtg + (size_t)scrow + s0 + (k2 - 4) * 4; dst = &sdt[buf][k2 - 4]; }
            }
            unsigned sm = (unsigned)__cvta_generic_to_shared(dst);
            asm volatile("cp.async.ca.shared.global [%0], [%1], 16;\n" ::"r"(sm), "l"(src));
        }
        asm volatile("cp.async.commit_group;\n");
    };

    float h[16];
#pragma unroll
    for (int i = 0; i < 16; i++) h[i] = 0.f;

    issue_chunk(0, 0);
    issue_chunk(1, 1);

    const int NCHUNK = LL / CH;
    for (int c = 0; c < NCHUNK; c++) {
        int buf = c & 1;
        asm volatile("cp.async.wait_group 1;\n");
        __syncthreads();
        int s0 = c * CH;
        const float* dAp = (const float*)sdA[buf];
        const float* dtp = (const float*)sdt[buf];
        for (int j = 0; j < CH; j++) {
            float dAv = dAp[j];
            float dtv = dtp[j];
            float xsv = ((const float*)sxs[buf][j])[p];
            float dtx = dtv * xsv;
            float a0 = 0.f, a1 = 0.f, a2 = 0.f, a3 = 0.f;
#pragma unroll
            for (int u = 0; u < 4; u++) {
                float4 Bv = sbc[buf][j][q * 4 + u];
                float4 Cv = sbc[buf][j][16 + q * 4 + u];
                float aa = 0.f;
                h[u * 4 + 0] = fmaf(dAv, h[u * 4 + 0], dtx * Bv.x); aa = fmaf(h[u * 4 + 0], Cv.x, aa);
                h[u * 4 + 1] = fmaf(dAv, h[u * 4 + 1], dtx * Bv.y); aa = fmaf(h[u * 4 + 1], Cv.y, aa);
                h[u * 4 + 2] = fmaf(dAv, h[u * 4 + 2], dtx * Bv.z); aa = fmaf(h[u * 4 + 2], Cv.z, aa);
                h[u * 4 + 3] = fmaf(dAv, h[u * 4 + 3], dtx * Bv.w); aa = fmaf(h[u * 4 + 3], Cv.w, aa);
                if (u == 0) a0 = aa; else if (u == 1) a1 = aa; else if (u == 2) a2 = aa; else a3 = aa;
            }
            float acc = (a0 + a1) + (a2 + a3);
            acc += __shfl_xor_sync(~0u, acc, 1);
            acc += __shfl_xor_sync(~0u, acc, 2);
            if (q == 0)
                ys[(size_t)((b << 11) + s0 + j) * DIN + hh * 64 + p] = acc + Dh * xsv;
        }
        __syncthreads();
        if (c + 2 < NCHUNK) issue_chunk(c + 2, buf);
        else asm volatile("cp.async.commit_group;\n");
    }
}

// ---------------- gating + inner rmsnorm: yn = rmsnorm(y * silu(z)) * norm_w ----------------
__global__ __launch_bounds__(256) void gate_norm_kernel(
    const float* __restrict__ ys0, const float* __restrict__ ys1,
    const float* __restrict__ zx0, const float* __restrict__ zx1,
    const float* __restrict__ nwf, const float* __restrict__ nwb,
    float* __restrict__ yn0, float* __restrict__ yn1) {
    int blk = blockIdx.x;
    int d = blk >> 12;
    int t = blk & 4095;
    const float* ys = d ? ys1 : ys0;
    const float* zx = d ? zx1 : zx0;
    const float* nw = d ? nwb : nwf;
    float* yn = d ? yn1 : yn0;
    int tid = threadIdx.x;
    float g[4];
    float ss = 0.f;
#pragma unroll
    for (int it = 0; it < 4; it++) {
        int j = tid + it * 256;
        float y = ys[(size_t)t * DIN + j];
        float z = zx[(size_t)t * DPROJ + j];
        float gz = z / (1.f + expf(-z));
        float v = y * gz;
        g[it] = v;
        ss += v * v;
    }
#pragma unroll
    for (int o = 16; o > 0; o >>= 1) ss += __shfl_xor_sync(~0u, ss, o);
    __shared__ float ws[8];
    if ((tid & 31) == 0) ws[tid >> 5] = ss;
    __syncthreads();
    float tot = 0.f;
#pragma unroll
    for (int w = 0; w < 8; w++) tot += ws[w];
    float sc = rsqrtf(tot / (float)DIN + EPSF);
#pragma unroll
    for (int it = 0; it < 4; it++) {
        int j = tid + it * 256;
        yn[(size_t)t * DIN + j] = g[it] * sc * nw[j];
    }
}

// ---------------- host launch ----------------
extern "C" void kernel_launch(void* const* d_in, const int* in_sizes, int n_in,
                              void* d_out, int out_size) {
    // Detect input ordering: signature order has fwd_in_w (2192*512) at index 2,
    // dict order has proj_w (512*1024) there.
    bool sig = (in_sizes[2] == DPROJ * DM);
    const float* x = (const float*)d_in[0];
    const float* nw = (const float*)d_in[1];
    int bf = sig ? 2 : 4;
    int bw = sig ? 10 : 12;
    const float* f_in_w = (const float*)d_in[bf + 0];
    const float* f_cw   = (const float*)d_in[bf + 1];
    const float* f_cb   = (const float*)d_in[bf + 2];
    const float* f_dtb  = (const float*)d_in[bf + 3];
    const float* f_Al   = (const float*)d_in[bf + 4];
    const float* f_D    = (const float*)d_in[bf + 5];
    const float* f_nw   = (const float*)d_in[bf + 6];
    const float* f_ow   = (const float*)d_in[bf + 7];
    const float* b_in_w = (const float*)d_in[bw + 0];
    const float* b_cw   = (const float*)d_in[bw + 1];
    const float* b_cb   = (const float*)d_in[bw + 2];
    const float* b_dtb  = (const float*)d_in[bw + 3];
    const float* b_Al   = (const float*)d_in[bw + 4];
    const float* b_D    = (const float*)d_in[bw + 5];
    const float* b_nw   = (const float*)d_in[bw + 6];
    const float* b_ow   = (const float*)d_in[bw + 7];
    const float* pw = (const float*)d_in[sig ? 18 : 2];
    const float* pb = (const float*)d_in[sig ? 19 : 3];

    float *xn, *zx0, *zx1, *xbc0, *xbc1, *dtg, *dAg, *ys0, *ys1, *yn0, *yn1, *od0, *od1;
    cudaGetSymbolAddress((void**)&xn, g_xn);
    cudaGetSymbolAddress((void**)&zx0, g_zx0);
    cudaGetSymbolAddress((void**)&zx1, g_zx1);
    cudaGetSymbolAddress((void**)&xbc0, g_xbc0);
    cudaGetSymbolAddress((void**)&xbc1, g_xbc1);
    cudaGetSymbolAddress((void**)&dtg, g_dt);
    cudaGetSymbolAddress((void**)&dAg, g_dA);
    cudaGetSymbolAddress((void**)&ys0, g_ys0);
    cudaGetSymbolAddress((void**)&ys1, g_ys1);
    cudaGetSymbolAddress((void**)&yn0, g_yn0);
    cudaGetSymbolAddress((void**)&yn1, g_yn1);
    cudaGetSymbolAddress((void**)&od0, g_od0);
    cudaGetSymbolAddress((void**)&od1, g_od1);

    rms_x_kernel<<<TT, 128>>>(x, nw, xn);

    // N = 2192 -> 35 tiles of 64 (last tile partially masked)
    gemm_nt<<<dim3((DPROJ + 63) / 64, TT / 64), 256>>>(xn, nullptr, f_in_w, zx0, DPROJ, DM, 0, nullptr, nullptr);
    gemm_nt<<<dim3((DPROJ + 63) / 64, TT / 64), 256>>>(xn, nullptr, b_in_w, zx1, DPROJ, DM, 1, nullptr, nullptr);

    conv_silu_kernel<<<(2 * TT * DCONV + 255) / 256, 256>>>(zx0, zx1, f_cw, f_cb, b_cw, b_cb, xbc0, xbc1);
    dt_kernel<<<(2 * TT * NH + 255) / 256, 256>>>(zx0, zx1, f_dtb, f_Al, b_dtb, b_Al, dtg, dAg);

    scan_kernel<<<64, 256>>>(xbc0, xbc1, dtg, dAg, f_D, b_D, ys0, ys1);

    gate_norm_kernel<<<2 * TT, 256>>>(ys0, ys1, zx0, zx1, f_nw, b_nw, yn0, yn1);

    gemm_nt<<<dim3(DM / 64, TT / 64), 256>>>(yn0, nullptr, f_ow, od0, DM, DIN, 0, nullptr, nullptr);
    gemm_nt<<<dim3(DM / 64, TT / 64), 256>>>(yn1, nullptr, b_ow, od1, DM, DIN, 0, nullptr, nullptr);

    gemm_nt<<<dim3(DM / 64, TT / 64), 256>>>(od0, od1, pw, (float*)d_out, DM, DIN, 2, pb, x);
}

// round 3
// speedup vs baseline: 1.6523x; 1.6523x over previous
#include <cuda_runtime.h>
#include <cuda_bf16.h>
#include <cstdint>

#define BB 2
#define LL 2048
#define TT 4096
#define DM 512
#define DIN 1024
#define NH 16
#define HD 64
#define DS 64
#define DCONV 1152
#define DPROJ 2192
#define EPSF 1e-5f
#define CH 16

// ---------------- scratch (static __device__ arrays; allocation-free) ----------------
__device__ float g_xn[TT * DM];
__device__ float g_zx0[TT * DPROJ];
__device__ float g_zx1[TT * DPROJ];
__device__ float g_xbc0[TT * DCONV];
__device__ float g_xbc1[TT * DCONV];
__device__ float g_dt[2 * BB * NH * LL];
__device__ float g_dA[2 * BB * NH * LL];
__device__ float g_ys0[TT * DIN];
__device__ float g_ys1[TT * DIN];
__device__ float g_yn0[TT * DIN];
__device__ float g_yn1[TT * DIN];
__device__ float g_od0[TT * DM];
__device__ float g_od1[TT * DM];

// ---------------- input rmsnorm: xn = rmsnorm(x) * norm_w ----------------
__global__ void rms_x_kernel(const float* __restrict__ x, const float* __restrict__ nw,
                             float* __restrict__ xn) {
    int t = blockIdx.x;
    int tid = threadIdx.x;
    float v[4];
    float ss = 0.f;
#pragma unroll
    for (int it = 0; it < 4; it++) {
        v[it] = x[(size_t)t * DM + tid + it * 128];
        ss += v[it] * v[it];
    }
#pragma unroll
    for (int o = 16; o > 0; o >>= 1) ss += __shfl_xor_sync(~0u, ss, o);
    __shared__ float ws[4];
    if ((tid & 31) == 0) ws[tid >> 5] = ss;
    __syncthreads();
    float tot = ws[0] + ws[1] + ws[2] + ws[3];
    float sc = rsqrtf(tot / (float)DM + EPSF);
#pragma unroll
    for (int it = 0; it < 4; it++) {
        int j = tid + it * 128;
        xn[(size_t)t * DM + j] = v[it] * sc * nw[j];
    }
}

__device__ __forceinline__ uint32_t f2tf32(float x) {
    uint32_t r;
    asm("cvt.rna.tf32.f32 %0, %1;\n" : "=r"(r) : "f"(x));
    return r;
}

// ---------------- tf32 tensor-core NT GEMM: C[m,n] = sum_k A[m,k] * W[n,k] ----------------
// Tile 128x128x16, 8 warps (4m x 2n), warp tile 32x64 via mma.m16n8k8.
// mode 0: A row = m
// mode 1: A row flipped within batch (bwd in-proj)
// mode 2: concat final proj: k<512 from A (row m), k>=512 from A2 (row flipped), stride 512
__global__ __launch_bounds__(256) void gemm_tf32(
    const float* __restrict__ A, const float* __restrict__ A2,
    const float* __restrict__ W, float* __restrict__ C,
    int N, int K, int mode,
    const float* __restrict__ bias, const float* __restrict__ resid) {
    __shared__ uint32_t sA[16][136];   // [k][m], bank = (8k + m) % 32 -> conflict-free frags
    __shared__ uint32_t sB[16][136];   // [k][n]
    int tid = threadIdx.x;
    int m0 = blockIdx.y * 128, n0 = blockIdx.x * 128;
    int warp = tid >> 5, lane = tid & 31;
    int wm = (warp & 3) * 32, wn = (warp >> 2) * 64;
    int tg = lane >> 2, tk = lane & 3;

    float acc[2][8][4];
#pragma unroll
    for (int mt = 0; mt < 2; mt++)
#pragma unroll
        for (int nt = 0; nt < 8; nt++)
#pragma unroll
            for (int r = 0; r < 4; r++) acc[mt][nt][r] = 0.f;

    int lrow = tid >> 1;        // 0..127
    int lkq = (tid & 1) * 8;    // 0 or 8

    // A-row global pointer base (row index mapping per mode)
    int gr = m0 + lrow;
    int bb = gr >> 11, sidx = gr & 2047;
    int frow = (bb << 11) + (2047 - sidx);
    const float* arow0;   // for k < 512 (or all k, modes 0/1)
    const float* arow1;   // for k >= 512 (mode 2 only)
    if (mode == 2) {
        arow0 = A + (size_t)gr * 512;
        arow1 = A2 + (size_t)frow * 512 - 512;   // index with k directly
    } else {
        int row = (mode == 1) ? frow : gr;
        arow0 = A + (size_t)row * K;
        arow1 = nullptr;
    }
    int nr = n0 + lrow;
    const float* wrow = W + (size_t)nr * K;
    bool nok = (nr < N);

    float ra[8], rb[8];

    auto gload = [&](int k0) {
        int kb = k0 + lkq;
        const float* ap = (mode == 2 && kb >= 512) ? arow1 : arow0;
        float4 v0 = *(const float4*)(ap + kb);
        float4 v1 = *(const float4*)(ap + kb + 4);
        ra[0] = v0.x; ra[1] = v0.y; ra[2] = v0.z; ra[3] = v0.w;
        ra[4] = v1.x; ra[5] = v1.y; ra[6] = v1.z; ra[7] = v1.w;
        if (nok) {
            float4 w0 = *(const float4*)(wrow + kb);
            float4 w1 = *(const float4*)(wrow + kb + 4);
            rb[0] = w0.x; rb[1] = w0.y; rb[2] = w0.z; rb[3] = w0.w;
            rb[4] = w1.x; rb[5] = w1.y; rb[6] = w1.z; rb[7] = w1.w;
        } else {
#pragma unroll
            for (int i = 0; i < 8; i++) rb[i] = 0.f;
        }
    };

    gload(0);
    for (int k0 = 0; k0 < K; k0 += 16) {
#pragma unroll
        for (int i = 0; i < 8; i++) {
            sA[lkq + i][lrow] = f2tf32(ra[i]);
            sB[lkq + i][lrow] = f2tf32(rb[i]);
        }
        __syncthreads();
        if (k0 + 16 < K) gload(k0 + 16);
#pragma unroll
        for (int ks = 0; ks < 2; ks++) {
            int kb = ks * 8;
            uint32_t af[2][4], bf[8][2];
#pragma unroll
            for (int mt = 0; mt < 2; mt++) {
                int mb = wm + mt * 16 + tg;
                af[mt][0] = sA[kb + tk][mb];
                af[mt][1] = sA[kb + tk][mb + 8];
                af[mt][2] = sA[kb + 4 + tk][mb];
                af[mt][3] = sA[kb + 4 + tk][mb + 8];
            }
#pragma unroll
            for (int nt = 0; nt < 8; nt++) {
                int nb = wn + nt * 8 + tg;
                bf[nt][0] = sB[kb + tk][nb];
                bf[nt][1] = sB[kb + 4 + tk][nb];
            }
#pragma unroll
            for (int mt = 0; mt < 2; mt++)
#pragma unroll
                for (int nt = 0; nt < 8; nt++) {
                    asm volatile(
                        "mma.sync.aligned.m16n8k8.row.col.f32.tf32.tf32.f32 "
                        "{%0,%1,%2,%3}, {%4,%5,%6,%7}, {%8,%9}, {%0,%1,%2,%3};\n"
                        : "+f"(acc[mt][nt][0]), "+f"(acc[mt][nt][1]),
                          "+f"(acc[mt][nt][2]), "+f"(acc[mt][nt][3])
                        : "r"(af[mt][0]), "r"(af[mt][1]), "r"(af[mt][2]), "r"(af[mt][3]),
                          "r"(bf[nt][0]), "r"(bf[nt][1]));
                }
        }
        __syncthreads();
    }

    // epilogue
#pragma unroll
    for (int mt = 0; mt < 2; mt++) {
        int r0 = m0 + wm + mt * 16 + tg;
#pragma unroll
        for (int nt = 0; nt < 8; nt++) {
            int c0 = n0 + wn + nt * 8 + 2 * tk;
            if (c0 >= N) continue;
#pragma unroll
            for (int half = 0; half < 2; half++) {
                int r = r0 + half * 8;
                float v0 = acc[mt][nt][half * 2 + 0];
                float v1 = acc[mt][nt][half * 2 + 1];
                if (bias) { v0 += bias[c0]; v1 += bias[c0 + 1]; }
                if (resid) {
                    v0 += resid[(size_t)r * N + c0];
                    v1 += resid[(size_t)r * N + c0 + 1];
                }
                C[(size_t)r * N + c0] = v0;
                C[(size_t)r * N + c0 + 1] = v1;
            }
        }
    }
}

// ---------------- causal depthwise conv (width 4) + bias + SiLU ----------------
__global__ void conv_silu_kernel(const float* __restrict__ zx0, const float* __restrict__ zx1,
                                 const float* __restrict__ cwf, const float* __restrict__ cbf,
                                 const float* __restrict__ cwb, const float* __restrict__ cbb,
                                 float* __restrict__ xbc0, float* __restrict__ xbc1) {
    int idx = blockIdx.x * blockDim.x + threadIdx.x;
    const int per = TT * DCONV;
    if (idx >= 2 * per) return;
    int d = idx / per;
    int r = idx - d * per;
    int t = r / DCONV;
    int c = r - t * DCONV;
    int b = t >> 11, s = t & 2047;
    const float* zx = d ? zx1 : zx0;
    const float* cw = d ? cwb : cwf;
    const float* cb = d ? cbb : cbf;
    float acc = cb[c];
#pragma unroll
    for (int i = 0; i < 4; i++) {
        int ss = s - 3 + i;
        if (ss >= 0)
            acc = fmaf(cw[c * 4 + i], zx[(size_t)((b << 11) + ss) * DPROJ + DIN + c], acc);
    }
    float v = acc / (1.f + expf(-acc));
    (d ? xbc1 : xbc0)[(size_t)t * DCONV + c] = v;
}

// ---------------- dt/dA precompute ----------------
__global__ void dt_kernel(const float* __restrict__ zx0, const float* __restrict__ zx1,
                          const float* __restrict__ dtbf, const float* __restrict__ Alf,
                          const float* __restrict__ dtbb, const float* __restrict__ Alb,
                          float* __restrict__ dtg, float* __restrict__ dAg) {
    int idx = blockIdx.x * blockDim.x + threadIdx.x;
    if (idx >= 2 * TT * NH) return;
    int d = idx / (TT * NH);
    int r = idx - d * TT * NH;
    int t = r / NH;
    int h = r - t * NH;
    int b = t >> 11, s = t & 2047;
    const float* zx = d ? zx1 : zx0;
    float raw = zx[(size_t)t * DPROJ + (DPROJ - NH) + h] + (d ? dtbb : dtbf)[h];
    float dtv = (raw > 20.f) ? raw : log1pf(expf(raw));
    float dAv = expf(-expf((d ? Alb : Alf)[h]) * dtv);
    int row = ((d * BB + b) * NH + h);
    dtg[(size_t)row * LL + s] = dtv;
    dAg[(size_t)row * LL + s] = dAv;
}

// ---------------- sequential SSM scan, one CTA per (dir, b, head) ----------------
__global__ __launch_bounds__(256) void scan_kernel(
    const float* __restrict__ xbc0, const float* __restrict__ xbc1,
    const float* __restrict__ dtg, const float* __restrict__ dAg,
    const float* __restrict__ Df, const float* __restrict__ Db,
    float* __restrict__ ys0, float* __restrict__ ys1) {
    int bid = blockIdx.x;
    int d = bid >> 5;
    int b = (bid >> 4) & 1;
    int hh = bid & 15;
    const float* xbc = d ? xbc1 : xbc0;
    float* ys = d ? ys1 : ys0;
    float Dh = (d ? Db : Df)[hh];
    int tid = threadIdx.x;
    int p = tid >> 2, q = tid & 3;
    int scrow = ((d * BB + b) * NH + hh) * LL;

    __shared__ float4 sxs[2][CH][16];
    __shared__ float4 sbc[2][CH][32];
    __shared__ float4 sdA[2][4];
    __shared__ float4 sdt[2][4];

    auto issue_chunk = [&](int c, int buf) {
        int s0 = c * CH;
        for (int ii = tid; ii < 776; ii += 256) {
            const float* src;
            void* dst;
            if (ii < 768) {
                int j = ii / 48, w = ii - j * 48;
                size_t rowb = (size_t)((b << 11) + s0 + j) * DCONV;
                if (w < 16) { src = xbc + rowb + hh * 64 + w * 4; dst = &sxs[buf][j][w]; }
                else        { src = xbc + rowb + 1024 + (w - 16) * 4; dst = &sbc[buf][j][w - 16]; }
            } else {
                int k2 = ii - 768;
                if (k2 < 4) { src = dAg + (size_t)scrow + s0 + k2 * 4; dst = &sdA[buf][k2]; }
                else        { src = dtg + (size_t)scrow + s0 + (k2 - 4) * 4; dst = &sdt[buf][k2 - 4]; }
            }
            unsigned sm = (unsigned)__cvta_generic_to_shared(dst);
            asm volatile("cp.async.ca.shared.global [%0], [%1], 16;\n" ::"r"(sm), "l"(src));
        }
        asm volatile("cp.async.commit_group;\n");
    };

    float h[16];
#pragma unroll
    for (int i = 0; i < 16; i++) h[i] = 0.f;

    issue_chunk(0, 0);
    issue_chunk(1, 1);

    const int NCHUNK = LL / CH;
    for (int c = 0; c < NCHUNK; c++) {
        int buf = c & 1;
        asm volatile("cp.async.wait_group 1;\n");
        __syncthreads();
        int s0 = c * CH;
        const float* dAp = (const float*)sdA[buf];
        const float* dtp = (const float*)sdt[buf];
        for (int j = 0; j < CH; j++) {
            float dAv = dAp[j];
            float dtv = dtp[j];
            float xsv = ((const float*)sxs[buf][j])[p];
            float dtx = dtv * xsv;
            float a0 = 0.f, a1 = 0.f, a2 = 0.f, a3 = 0.f;
#pragma unroll
            for (int u = 0; u < 4; u++) {
                float4 Bv = sbc[buf][j][q * 4 + u];
                float4 Cv = sbc[buf][j][16 + q * 4 + u];
                float aa = 0.f;
                h[u * 4 + 0] = fmaf(dAv, h[u * 4 + 0], dtx * Bv.x); aa = fmaf(h[u * 4 + 0], Cv.x, aa);
                h[u * 4 + 1] = fmaf(dAv, h[u * 4 + 1], dtx * Bv.y); aa = fmaf(h[u * 4 + 1], Cv.y, aa);
                h[u * 4 + 2] = fmaf(dAv, h[u * 4 + 2], dtx * Bv.z); aa = fmaf(h[u * 4 + 2], Cv.z, aa);
                h[u * 4 + 3] = fmaf(dAv, h[u * 4 + 3], dtx * Bv.w); aa = fmaf(h[u * 4 + 3], Cv.w, aa);
                if (u == 0) a0 = aa; else if (u == 1) a1 = aa; else if (u == 2) a2 = aa; else a3 = aa;
            }
            float acc = (a0 + a1) + (a2 + a3);
            acc += __shfl_xor_sync(~0u, acc, 1);
            acc += __shfl_xor_sync(~0u, acc, 2);
            if (q == 0)
                ys[(size_t)((b << 11) + s0 + j) * DIN + hh * 64 + p] = acc + Dh * xsv;
        }
        __syncthreads();
        if (c + 2 < NCHUNK) issue_chunk(c + 2, buf);
        else asm volatile("cp.async.commit_group;\n");
    }
}

// ---------------- gating + inner rmsnorm ----------------
__global__ __launch_bounds__(256) void gate_norm_kernel(
    const float* __restrict__ ys0, const float* __restrict__ ys1,
    const float* __restrict__ zx0, const float* __restrict__ zx1,
    const float* __restrict__ nwf, const float* __restrict__ nwb,
    float* __restrict__ yn0, float* __restrict__ yn1) {
    int blk = blockIdx.x;
    int d = blk >> 12;
    int t = blk & 4095;
    const float* ys = d ? ys1 : ys0;
    const float* zx = d ? zx1 : zx0;
    const float* nw = d ? nwb : nwf;
    float* yn = d ? yn1 : yn0;
    int tid = threadIdx.x;
    float g[4];
    float ss = 0.f;
#pragma unroll
    for (int it = 0; it < 4; it++) {
        int j = tid + it * 256;
        float y = ys[(size_t)t * DIN + j];
        float z = zx[(size_t)t * DPROJ + j];
        float gz = z / (1.f + expf(-z));
        float v = y * gz;
        g[it] = v;
        ss += v * v;
    }
#pragma unroll
    for (int o = 16; o > 0; o >>= 1) ss += __shfl_xor_sync(~0u, ss, o);
    __shared__ float ws[8];
    if ((tid & 31) == 0) ws[tid >> 5] = ss;
    __syncthreads();
    float tot = 0.f;
#pragma unroll
    for (int w = 0; w < 8; w++) tot += ws[w];
    float sc = rsqrtf(tot / (float)DIN + EPSF);
#pragma unroll
    for (int it = 0; it < 4; it++) {
        int j = tid + it * 256;
        yn[(size_t)t * DIN + j] = g[it] * sc * nw[j];
    }
}

// ---------------- host launch ----------------
extern "C" void kernel_launch(void* const* d_in, const int* in_sizes, int n_in,
                              void* d_out, int out_size) {
    bool sig = (in_sizes[2] == DPROJ * DM);
    const float* x = (const float*)d_in[0];
    const float* nw = (const float*)d_in[1];
    int bf = sig ? 2 : 4;
    int bw = sig ? 10 : 12;
    const float* f_in_w = (const float*)d_in[bf + 0];
    const float* f_cw   = (const float*)d_in[bf + 1];
    const float* f_cb   = (const float*)d_in[bf + 2];
    const float* f_dtb  = (const float*)d_in[bf + 3];
    const float* f_Al   = (const float*)d_in[bf + 4];
    const float* f_D    = (const float*)d_in[bf + 5];
    const float* f_nw   = (const float*)d_in[bf + 6];
    const float* f_ow   = (const float*)d_in[bf + 7];
    const float* b_in_w = (const float*)d_in[bw + 0];
    const float* b_cw   = (const float*)d_in[bw + 1];
    const float* b_cb   = (const float*)d_in[bw + 2];
    const float* b_dtb  = (const float*)d_in[bw + 3];
    const float* b_Al   = (const float*)d_in[bw + 4];
    const float* b_D    = (const float*)d_in[bw + 5];
    const float* b_nw   = (const float*)d_in[bw + 6];
    const float* b_ow   = (const float*)d_in[bw + 7];
    const float* pw = (const float*)d_in[sig ? 18 : 2];
    const float* pb = (const float*)d_in[sig ? 19 : 3];

    float *xn, *zx0, *zx1, *xbc0, *xbc1, *dtg, *dAg, *ys0, *ys1, *yn0, *yn1, *od0, *od1;
    cudaGetSymbolAddress((void**)&xn, g_xn);
    cudaGetSymbolAddress((void**)&zx0, g_zx0);
    cudaGetSymbolAddress((void**)&zx1, g_zx1);
    cudaGetSymbolAddress((void**)&xbc0, g_xbc0);
    cudaGetSymbolAddress((void**)&xbc1, g_xbc1);
    cudaGetSymbolAddress((void**)&dtg, g_dt);
    cudaGetSymbolAddress((void**)&dAg, g_dA);
    cudaGetSymbolAddress((void**)&ys0, g_ys0);
    cudaGetSymbolAddress((void**)&ys1, g_ys1);
    cudaGetSymbolAddress((void**)&yn0, g_yn0);
    cudaGetSymbolAddress((void**)&yn1, g_yn1);
    cudaGetSymbolAddress((void**)&od0, g_od0);
    cudaGetSymbolAddress((void**)&od1, g_od1);

    rms_x_kernel<<<TT, 128>>>(x, nw, xn);

    gemm_tf32<<<dim3((DPROJ + 127) / 128, TT / 128), 256>>>(xn, nullptr, f_in_w, zx0, DPROJ, DM, 0, nullptr, nullptr);
    gemm_tf32<<<dim3((DPROJ + 127) / 128, TT / 128), 256>>>(xn, nullptr, b_in_w, zx1, DPROJ, DM, 1, nullptr, nullptr);

    conv_silu_kernel<<<(2 * TT * DCONV + 255) / 256, 256>>>(zx0, zx1, f_cw, f_cb, b_cw, b_cb, xbc0, xbc1);
    dt_kernel<<<(2 * TT * NH + 255) / 256, 256>>>(zx0, zx1, f_dtb, f_Al, b_dtb, b_Al, dtg, dAg);

    scan_kernel<<<64, 256>>>(xbc0, xbc1, dtg, dAg, f_D, b_D, ys0, ys1);

    gate_norm_kernel<<<2 * TT, 256>>>(ys0, ys1, zx0, zx1, f_nw, b_nw, yn0, yn1);

    gemm_tf32<<<dim3(DM / 128, TT / 128), 256>>>(yn0, nullptr, f_ow, od0, DM, DIN, 0, nullptr, nullptr);
    gemm_tf32<<<dim3(DM / 128, TT / 128), 256>>>(yn1, nullptr, b_ow, od1, DM, DIN, 0, nullptr, nullptr);

    gemm_tf32<<<dim3(DM / 128, TT / 128), 256>>>(od0, od1, pw, (float*)d_out, DM, DIN, 2, pb, x);
}

// round 4
// speedup vs baseline: 1.6753x; 1.0139x over previous
#include <cuda_runtime.h>
#include <cuda_bf16.h>
#include <cstdint>

#define BB 2
#define LL 2048
#define TT 4096
#define DM 512
#define DIN 1024
#define NH 16
#define HD 64
#define DS 64
#define DCONV 1152
#define DPROJ 2192
#define EPSF 1e-5f
#define CH 16

// ---------------- scratch ----------------
__device__ float g_xn[TT * DM];
__device__ float g_zx0[TT * DPROJ];
__device__ float g_zx1[TT * DPROJ];
__device__ float g_xbc0[TT * DCONV];
__device__ float g_xbc1[TT * DCONV];
__device__ float g_dt[2 * BB * NH * LL];
__device__ float g_dA[2 * BB * NH * LL];
__device__ float g_ys0[TT * DIN];
__device__ float g_ys1[TT * DIN];
__device__ float g_yn0[TT * DIN];
__device__ float g_yn1[TT * DIN];
__device__ float g_od0[TT * DM];
__device__ float g_od1[TT * DM];

// ---------------- input rmsnorm ----------------
__global__ void rms_x_kernel(const float* __restrict__ x, const float* __restrict__ nw,
                             float* __restrict__ xn) {
    int t = blockIdx.x;
    int tid = threadIdx.x;
    float v[4];
    float ss = 0.f;
#pragma unroll
    for (int it = 0; it < 4; it++) {
        v[it] = x[(size_t)t * DM + tid + it * 128];
        ss += v[it] * v[it];
    }
#pragma unroll
    for (int o = 16; o > 0; o >>= 1) ss += __shfl_xor_sync(~0u, ss, o);
    __shared__ float ws[4];
    if ((tid & 31) == 0) ws[tid >> 5] = ss;
    __syncthreads();
    float tot = ws[0] + ws[1] + ws[2] + ws[3];
    float sc = rsqrtf(tot / (float)DM + EPSF);
#pragma unroll
    for (int it = 0; it < 4; it++) {
        int j = tid + it * 128;
        xn[(size_t)t * DM + j] = v[it] * sc * nw[j];
    }
}

// ---------------- pipelined tf32 NT GEMM ----------------
// C[m,n] = sum_k A[m,k] * W[n,k].  BN=128, BM template (128 or 64).
// 3-stage cp.async pipeline; smem row-major [row][k] stride 20 floats (conflict-free frags).
// Raw f32 bits fed to mma.tf32 (HW truncation, no cvt).
// mode 0: A row = m;  mode 1: row flipped within batch;  mode 2: concat (A | A2-flipped), stride 512.
template <int BM>
__global__ __launch_bounds__(256) void gemm_tf32p(
    const float* __restrict__ A, const float* __restrict__ A2,
    const float* __restrict__ W, float* __restrict__ C,
    int N, int K, int mode,
    const float* __restrict__ bias, const float* __restrict__ resid) {
    constexpr int BN = 128;
    constexpr int STR = 20;      // floats per 16-float row (bank-conflict-free pad)
    constexpr int STAGES = 3;
    constexpr int NT = (BM == 128) ? 8 : 4;
    extern __shared__ float smem[];
    float* sAb = smem;                          // [STAGES][BM*STR]
    float* sBb = smem + STAGES * BM * STR;      // [STAGES][BN*STR]

    int tid = threadIdx.x;
    int warp = tid >> 5, lane = tid & 31;
    int m0 = blockIdx.y * BM, n0 = blockIdx.x * BN;
    int tg = lane >> 2, tk = lane & 3;
    int wm, wn;
    if (BM == 128) { wm = (warp & 3) * 32; wn = (warp >> 2) * 64; }
    else           { wm = (warp & 1) * 32; wn = (warp >> 1) * 32; }

    float acc[2][NT][4];
#pragma unroll
    for (int mt = 0; mt < 2; mt++)
#pragma unroll
        for (int nt = 0; nt < NT; nt++)
#pragma unroll
            for (int r = 0; r < 4; r++) acc[mt][nt][r] = 0.f;

    // A-load mapping
    int lrA = (BM == 128) ? (tid >> 1) : (tid >> 2);
    int kA0 = (BM == 128) ? ((tid & 1) * 8) : ((tid & 3) * 4);
    int gr = m0 + lrA;
    int bb = gr >> 11, sidx = gr & 2047;
    int frow = (bb << 11) + (2047 - sidx);
    const float* arow0;
    const float* arow1 = nullptr;
    if (mode == 2) {
        arow0 = A + (size_t)gr * 512;
        arow1 = A2 + (size_t)frow * 512 - 512;
    } else {
        int row = (mode == 1) ? frow : gr;
        arow0 = A + (size_t)row * K;
    }
    // B-load mapping (BN=128 always: 2 chunks/thread)
    int lrB = tid >> 1;
    int kB0 = (tid & 1) * 8;
    int nr = n0 + lrB;
    const float* wrow = W + (size_t)(nr < N ? nr : (N - 1)) * K;
    int wsz = (nr < N) ? 16 : 0;

    auto issue = [&](int k0, int stg) {
        float* dA = sAb + stg * BM * STR + lrA * STR;
#pragma unroll
        for (int c = 0; c < (BM == 128 ? 2 : 1); c++) {
            int kb = k0 + kA0 + c * 4;
            const float* src = (mode == 2 && kb >= 512) ? (arow1 + kb) : (arow0 + kb);
            unsigned d = (unsigned)__cvta_generic_to_shared(dA + kA0 + c * 4);
            asm volatile("cp.async.ca.shared.global [%0], [%1], 16;\n" ::"r"(d), "l"(src));
        }
        float* dB = sBb + stg * BN * STR + lrB * STR;
#pragma unroll
        for (int c = 0; c < 2; c++) {
            int kb = k0 + kB0 + c * 4;
            unsigned d = (unsigned)__cvta_generic_to_shared(dB + kB0 + c * 4);
            asm volatile("cp.async.ca.shared.global [%0], [%1], 16, %2;\n"
                         ::"r"(d), "l"(wrow + kb), "r"(wsz));
        }
        asm volatile("cp.async.commit_group;\n");
    };

    int NC = K / 16;
    issue(0, 0);
    issue(16, 1);

    for (int c = 0; c < NC; c++) {
        asm volatile("cp.async.wait_group 1;\n");
        __syncthreads();
        if (c + 2 < NC) issue((c + 2) * 16, (c + 2) % STAGES);
        const float* pA = sAb + (c % STAGES) * BM * STR;
        const float* pB = sBb + (c % STAGES) * BN * STR;
#pragma unroll
        for (int ks = 0; ks < 2; ks++) {
            int kb = ks * 8;
            uint32_t af[2][4], bf[NT][2];
#pragma unroll
            for (int mt = 0; mt < 2; mt++) {
                int mb = wm + mt * 16 + tg;
                af[mt][0] = __float_as_uint(pA[mb * STR + kb + tk]);
                af[mt][1] = __float_as_uint(pA[(mb + 8) * STR + kb + tk]);
                af[mt][2] = __float_as_uint(pA[mb * STR + kb + tk + 4]);
                af[mt][3] = __float_as_uint(pA[(mb + 8) * STR + kb + tk + 4]);
            }
#pragma unroll
            for (int nt = 0; nt < NT; nt++) {
                int nb = wn + nt * 8 + tg;
                bf[nt][0] = __float_as_uint(pB[nb * STR + kb + tk]);
                bf[nt][1] = __float_as_uint(pB[nb * STR + kb + tk + 4]);
            }
#pragma unroll
            for (int mt = 0; mt < 2; mt++)
#pragma unroll
                for (int nt = 0; nt < NT; nt++) {
                    asm volatile(
                        "mma.sync.aligned.m16n8k8.row.col.f32.tf32.tf32.f32 "
                        "{%0,%1,%2,%3}, {%4,%5,%6,%7}, {%8,%9}, {%0,%1,%2,%3};\n"
                        : "+f"(acc[mt][nt][0]), "+f"(acc[mt][nt][1]),
                          "+f"(acc[mt][nt][2]), "+f"(acc[mt][nt][3])
                        : "r"(af[mt][0]), "r"(af[mt][1]), "r"(af[mt][2]), "r"(af[mt][3]),
                          "r"(bf[nt][0]), "r"(bf[nt][1]));
                }
        }
        __syncthreads();
    }

#pragma unroll
    for (int mt = 0; mt < 2; mt++) {
        int r0 = m0 + wm + mt * 16 + tg;
#pragma unroll
        for (int nt = 0; nt < NT; nt++) {
            int c0 = n0 + wn + nt * 8 + 2 * tk;
            if (c0 >= N) continue;
#pragma unroll
            for (int half = 0; half < 2; half++) {
                int r = r0 + half * 8;
                float v0 = acc[mt][nt][half * 2 + 0];
                float v1 = acc[mt][nt][half * 2 + 1];
                if (bias) { v0 += bias[c0]; v1 += bias[c0 + 1]; }
                if (resid) {
                    v0 += resid[(size_t)r * N + c0];
                    v1 += resid[(size_t)r * N + c0 + 1];
                }
                C[(size_t)r * N + c0] = v0;
                C[(size_t)r * N + c0 + 1] = v1;
            }
        }
    }
}

// ---------------- causal depthwise conv (width 4) + bias + SiLU ----------------
__global__ void conv_silu_kernel(const float* __restrict__ zx0, const float* __restrict__ zx1,
                                 const float* __restrict__ cwf, const float* __restrict__ cbf,
                                 const float* __restrict__ cwb, const float* __restrict__ cbb,
                                 float* __restrict__ xbc0, float* __restrict__ xbc1) {
    int idx = blockIdx.x * blockDim.x + threadIdx.x;
    const int per = TT * DCONV;
    if (idx >= 2 * per) return;
    int d = idx / per;
    int r = idx - d * per;
    int t = r / DCONV;
    int c = r - t * DCONV;
    int b = t >> 11, s = t & 2047;
    const float* zx = d ? zx1 : zx0;
    const float* cw = d ? cwb : cwf;
    const float* cb = d ? cbb : cbf;
    float acc = cb[c];
#pragma unroll
    for (int i = 0; i < 4; i++) {
        int ss = s - 3 + i;
        if (ss >= 0)
            acc = fmaf(cw[c * 4 + i], zx[(size_t)((b << 11) + ss) * DPROJ + DIN + c], acc);
    }
    float v = acc / (1.f + expf(-acc));
    (d ? xbc1 : xbc0)[(size_t)t * DCONV + c] = v;
}

// ---------------- dt/dA precompute ----------------
__global__ void dt_kernel(const float* __restrict__ zx0, const float* __restrict__ zx1,
                          const float* __restrict__ dtbf, const float* __restrict__ Alf,
                          const float* __restrict__ dtbb, const float* __restrict__ Alb,
                          float* __restrict__ dtg, float* __restrict__ dAg) {
    int idx = blockIdx.x * blockDim.x + threadIdx.x;
    if (idx >= 2 * TT * NH) return;
    int d = idx / (TT * NH);
    int r = idx - d * TT * NH;
    int t = r / NH;
    int h = r - t * NH;
    int b = t >> 11, s = t & 2047;
    const float* zx = d ? zx1 : zx0;
    float raw = zx[(size_t)t * DPROJ + (DPROJ - NH) + h] + (d ? dtbb : dtbf)[h];
    float dtv = (raw > 20.f) ? raw : log1pf(expf(raw));
    float dAv = expf(-expf((d ? Alb : Alf)[h]) * dtv);
    int row = ((d * BB + b) * NH + h);
    dtg[(size_t)row * LL + s] = dtv;
    dAg[(size_t)row * LL + s] = dAv;
}

// ---------------- sequential SSM scan ----------------
__global__ __launch_bounds__(256) void scan_kernel(
    const float* __restrict__ xbc0, const float* __restrict__ xbc1,
    const float* __restrict__ dtg, const float* __restrict__ dAg,
    const float* __restrict__ Df, const float* __restrict__ Db,
    float* __restrict__ ys0, float* __restrict__ ys1) {
    int bid = blockIdx.x;
    int d = bid >> 5;
    int b = (bid >> 4) & 1;
    int hh = bid & 15;
    const float* xbc = d ? xbc1 : xbc0;
    float* ys = d ? ys1 : ys0;
    float Dh = (d ? Db : Df)[hh];
    int tid = threadIdx.x;
    int p = tid >> 2, q = tid & 3;
    int scrow = ((d * BB + b) * NH + hh) * LL;

    __shared__ float4 sxs[2][CH][16];
    __shared__ float4 sbc[2][CH][32];
    __shared__ float4 sdA[2][4];
    __shared__ float4 sdt[2][4];

    auto issue_chunk = [&](int c, int buf) {
        int s0 = c * CH;
        for (int ii = tid; ii < 776; ii += 256) {
            const float* src;
            void* dst;
            if (ii < 768) {
                int j = ii / 48, w = ii - j * 48;
                size_t rowb = (size_t)((b << 11) + s0 + j) * DCONV;
                if (w < 16) { src = xbc + rowb + hh * 64 + w * 4; dst = &sxs[buf][j][w]; }
                else        { src = xbc + rowb + 1024 + (w - 16) * 4; dst = &sbc[buf][j][w - 16]; }
            } else {
                int k2 = ii - 768;
                if (k2 < 4) { src = dAg + (size_t)scrow + s0 + k2 * 4; dst = &sdA[buf][k2]; }
                else        { src = dtg + (size_t)scrow + s0 + (k2 - 4) * 4; dst = &sdt[buf][k2 - 4]; }
            }
            unsigned sm = (unsigned)__cvta_generic_to_shared(dst);
            asm volatile("cp.async.ca.shared.global [%0], [%1], 16;\n" ::"r"(sm), "l"(src));
        }
        asm volatile("cp.async.commit_group;\n");
    };

    float h[16];
#pragma unroll
    for (int i = 0; i < 16; i++) h[i] = 0.f;

    issue_chunk(0, 0);
    issue_chunk(1, 1);

    const int NCHUNK = LL / CH;
    for (int c = 0; c < NCHUNK; c++) {
        int buf = c & 1;
        asm volatile("cp.async.wait_group 1;\n");
        __syncthreads();
        int s0 = c * CH;
        const float* dAp = (const float*)sdA[buf];
        const float* dtp = (const float*)sdt[buf];
        for (int j = 0; j < CH; j++) {
            float dAv = dAp[j];
            float dtv = dtp[j];
            float xsv = ((const float*)sxs[buf][j])[p];
            float dtx = dtv * xsv;
            float a0 = 0.f, a1 = 0.f, a2 = 0.f, a3 = 0.f;
#pragma unroll
            for (int u = 0; u < 4; u++) {
                float4 Bv = sbc[buf][j][q * 4 + u];
                float4 Cv = sbc[buf][j][16 + q * 4 + u];
                float aa = 0.f;
                h[u * 4 + 0] = fmaf(dAv, h[u * 4 + 0], dtx * Bv.x); aa = fmaf(h[u * 4 + 0], Cv.x, aa);
                h[u * 4 + 1] = fmaf(dAv, h[u * 4 + 1], dtx * Bv.y); aa = fmaf(h[u * 4 + 1], Cv.y, aa);
                h[u * 4 + 2] = fmaf(dAv, h[u * 4 + 2], dtx * Bv.z); aa = fmaf(h[u * 4 + 2], Cv.z, aa);
                h[u * 4 + 3] = fmaf(dAv, h[u * 4 + 3], dtx * Bv.w); aa = fmaf(h[u * 4 + 3], Cv.w, aa);
                if (u == 0) a0 = aa; else if (u == 1) a1 = aa; else if (u == 2) a2 = aa; else a3 = aa;
            }
            float acc = (a0 + a1) + (a2 + a3);
            acc += __shfl_xor_sync(~0u, acc, 1);
            acc += __shfl_xor_sync(~0u, acc, 2);
            if (q == 0)
                ys[(size_t)((b << 11) + s0 + j) * DIN + hh * 64 + p] = acc + Dh * xsv;
        }
        __syncthreads();
        if (c + 2 < NCHUNK) issue_chunk(c + 2, buf);
        else asm volatile("cp.async.commit_group;\n");
    }
}

// ---------------- gating + inner rmsnorm ----------------
__global__ __launch_bounds__(256) void gate_norm_kernel(
    const float* __restrict__ ys0, const float* __restrict__ ys1,
    const float* __restrict__ zx0, const float* __restrict__ zx1,
    const float* __restrict__ nwf, const float* __restrict__ nwb,
    float* __restrict__ yn0, float* __restrict__ yn1) {
    int blk = blockIdx.x;
    int d = blk >> 12;
    int t = blk & 4095;
    const float* ys = d ? ys1 : ys0;
    const float* zx = d ? zx1 : zx0;
    const float* nw = d ? nwb : nwf;
    float* yn = d ? yn1 : yn0;
    int tid = threadIdx.x;
    float g[4];
    float ss = 0.f;
#pragma unroll
    for (int it = 0; it < 4; it++) {
        int j = tid + it * 256;
        float y = ys[(size_t)t * DIN + j];
        float z = zx[(size_t)t * DPROJ + j];
        float gz = z / (1.f + expf(-z));
        float v = y * gz;
        g[it] = v;
        ss += v * v;
    }
#pragma unroll
    for (int o = 16; o > 0; o >>= 1) ss += __shfl_xor_sync(~0u, ss, o);
    __shared__ float ws[8];
    if ((tid & 31) == 0) ws[tid >> 5] = ss;
    __syncthreads();
    float tot = 0.f;
#pragma unroll
    for (int w = 0; w < 8; w++) tot += ws[w];
    float sc = rsqrtf(tot / (float)DIN + EPSF);
#pragma unroll
    for (int it = 0; it < 4; it++) {
        int j = tid + it * 256;
        yn[(size_t)t * DIN + j] = g[it] * sc * nw[j];
    }
}

// ---------------- host launch ----------------
extern "C" void kernel_launch(void* const* d_in, const int* in_sizes, int n_in,
                              void* d_out, int out_size) {
    bool sig = (in_sizes[2] == DPROJ * DM);
    const float* x = (const float*)d_in[0];
    const float* nw = (const float*)d_in[1];
    int bf = sig ? 2 : 4;
    int bw = sig ? 10 : 12;
    const float* f_in_w = (const float*)d_in[bf + 0];
    const float* f_cw   = (const float*)d_in[bf + 1];
    const float* f_cb   = (const float*)d_in[bf + 2];
    const float* f_dtb  = (const float*)d_in[bf + 3];
    const float* f_Al   = (const float*)d_in[bf + 4];
    const float* f_D    = (const float*)d_in[bf + 5];
    const float* f_nw   = (const float*)d_in[bf + 6];
    const float* f_ow   = (const float*)d_in[bf + 7];
    const float* b_in_w = (const float*)d_in[bw + 0];
    const float* b_cw   = (const float*)d_in[bw + 1];
    const float* b_cb   = (const float*)d_in[bw + 2];
    const float* b_dtb  = (const float*)d_in[bw + 3];
    const float* b_Al   = (const float*)d_in[bw + 4];
    const float* b_D    = (const float*)d_in[bw + 5];
    const float* b_nw   = (const float*)d_in[bw + 6];
    const float* b_ow   = (const float*)d_in[bw + 7];
    const float* pw = (const float*)d_in[sig ? 18 : 2];
    const float* pb = (const float*)d_in[sig ? 19 : 3];

    float *xn, *zx0, *zx1, *xbc0, *xbc1, *dtg, *dAg, *ys0, *ys1, *yn0, *yn1, *od0, *od1;
    cudaGetSymbolAddress((void**)&xn, g_xn);
    cudaGetSymbolAddress((void**)&zx0, g_zx0);
    cudaGetSymbolAddress((void**)&zx1, g_zx1);
    cudaGetSymbolAddress((void**)&xbc0, g_xbc0);
    cudaGetSymbolAddress((void**)&xbc1, g_xbc1);
    cudaGetSymbolAddress((void**)&dtg, g_dt);
    cudaGetSymbolAddress((void**)&dAg, g_dA);
    cudaGetSymbolAddress((void**)&ys0, g_ys0);
    cudaGetSymbolAddress((void**)&ys1, g_ys1);
    cudaGetSymbolAddress((void**)&yn0, g_yn0);
    cudaGetSymbolAddress((void**)&yn1, g_yn1);
    cudaGetSymbolAddress((void**)&od0, g_od0);
    cudaGetSymbolAddress((void**)&od1, g_od1);

    const int SM128 = 3 * (128 * 20 + 128 * 20) * 4;   // 61440
    const int SM64  = 3 * (64 * 20 + 128 * 20) * 4;    // 46080
    cudaFuncSetAttribute(gemm_tf32p<128>, cudaFuncAttributeMaxDynamicSharedMemorySize, SM128);
    cudaFuncSetAttribute(gemm_tf32p<64>,  cudaFuncAttributeMaxDynamicSharedMemorySize, SM64);

    rms_x_kernel<<<TT, 128>>>(x, nw, xn);

    gemm_tf32p<128><<<dim3((DPROJ + 127) / 128, TT / 128), 256, SM128>>>(
        xn, nullptr, f_in_w, zx0, DPROJ, DM, 0, nullptr, nullptr);
    gemm_tf32p<128><<<dim3((DPROJ + 127) / 128, TT / 128), 256, SM128>>>(
        xn, nullptr, b_in_w, zx1, DPROJ, DM, 1, nullptr, nullptr);

    conv_silu_kernel<<<(2 * TT * DCONV + 255) / 256, 256>>>(zx0, zx1, f_cw, f_cb, b_cw, b_cb, xbc0, xbc1);
    dt_kernel<<<(2 * TT * NH + 255) / 256, 256>>>(zx0, zx1, f_dtb, f_Al, b_dtb, b_Al, dtg, dAg);

    scan_kernel<<<64, 256>>>(xbc0, xbc1, dtg, dAg, f_D, b_D, ys0, ys1);

    gate_norm_kernel<<<2 * TT, 256>>>(ys0, ys1, zx0, zx1, f_nw, b_nw, yn0, yn1);

    gemm_tf32p<64><<<dim3(DM / 128, TT / 64), 256, SM64>>>(
        yn0, nullptr, f_ow, od0, DM, DIN, 0, nullptr, nullptr);
    gemm_tf32p<64><<<dim3(DM / 128, TT / 64), 256, SM64>>>(
        yn1, nullptr, b_ow, od1, DM, DIN, 0, nullptr, nullptr);

    gemm_tf32p<64><<<dim3(DM / 128, TT / 64), 256, SM64>>>(
        od0, od1, pw, (float*)d_out, DM, DIN, 2, pb, x);
}